// round 8
// baseline (speedup 1.0000x reference)
#include <cuda_runtime.h>
#include <math.h>

#define EPS 1e-8f

// 2 lanes per row, 32 columns per lane, 16 rows per warp. Row processed in two
// 16-element batches to bound register pressure. 256-bit loads (R6-validated).
// Single xor-1 segmented reduction step. Quantum cos-product predicated to the
// even lane (holds raw cols 0..7 in its first batch).
__device__ __forceinline__ void ldg256(const float* __restrict__ p, float r[8]) {
    unsigned u0, u1, u2, u3, u4, u5, u6, u7;
    asm("ld.global.v8.b32 {%0,%1,%2,%3,%4,%5,%6,%7}, [%8];"
        : "=r"(u0), "=r"(u1), "=r"(u2), "=r"(u3),
          "=r"(u4), "=r"(u5), "=r"(u6), "=r"(u7)
        : "l"(p));
    r[0] = __uint_as_float(u0); r[1] = __uint_as_float(u1);
    r[2] = __uint_as_float(u2); r[3] = __uint_as_float(u3);
    r[4] = __uint_as_float(u4); r[5] = __uint_as_float(u5);
    r[6] = __uint_as_float(u6); r[7] = __uint_as_float(u7);
}

__global__ void __launch_bounds__(256) hybrid_rbf_kernel(
    const float* __restrict__ x,
    const float* __restrict__ y,
    float* __restrict__ out,
    int B)
{
    const int warp_id = (blockIdx.x * blockDim.x + threadIdx.x) >> 5;
    const int lane    = threadIdx.x & 31;
    const int group   = lane >> 1;   // 0..15 : row within the warp
    const int j       = lane & 1;    // 0..1  : 32-column half within the row
    const int row     = warp_id * 16 + group;
    if (row >= B) return;

    const float* __restrict__ xp = x + (size_t)row * 64 + j * 32;
    const float* __restrict__ yp = y + (size_t)row * 64 + j * 32;

    float sx = 0.f, sxx = 0.f, sy = 0.f, syy = 0.f, sxy = 0.f;
    float q = 0.f;

    // ---- Batch 0: elements 0..15 of this lane's 32-column half ----
    {
        float xa[16], ya[16];
        ldg256(xp,     xa);
        ldg256(xp + 8, xa + 8);
        ldg256(yp,     ya);
        ldg256(yp + 8, ya + 8);

        #pragma unroll
        for (int e = 0; e < 16; e++) {
            const float xv = xa[e], yv = ya[e];
            sx  += xv;
            sy  += yv;
            sxx = fmaf(xv, xv, sxx);
            syy = fmaf(yv, yv, syy);
            sxy = fmaf(xv, yv, sxy);
        }

        // Quantum term: even lane's first 8 elements are raw cols 0..7.
        if (j == 0) {
            q = __cosf(xa[0] - ya[0]) * __cosf(xa[1] - ya[1])
              * __cosf(xa[2] - ya[2]) * __cosf(xa[3] - ya[3])
              * __cosf(xa[4] - ya[4]) * __cosf(xa[5] - ya[5])
              * __cosf(xa[6] - ya[6]) * __cosf(xa[7] - ya[7]);
        }
    }

    // ---- Batch 1: elements 16..31 of this lane's half ----
    {
        float xa[16], ya[16];
        ldg256(xp + 16, xa);
        ldg256(xp + 24, xa + 8);
        ldg256(yp + 16, ya);
        ldg256(yp + 24, ya + 8);

        #pragma unroll
        for (int e = 0; e < 16; e++) {
            const float xv = xa[e], yv = ya[e];
            sx  += xv;
            sy  += yv;
            sxx = fmaf(xv, xv, sxx);
            syy = fmaf(yv, yv, syy);
            sxy = fmaf(xv, yv, sxy);
        }
    }

    // Segmented reduction: single xor-1 step pairs the two lanes of each row.
    sx  += __shfl_xor_sync(0xFFFFFFFFu, sx,  1);
    sy  += __shfl_xor_sync(0xFFFFFFFFu, sy,  1);
    sxx += __shfl_xor_sync(0xFFFFFFFFu, sxx, 1);
    syy += __shfl_xor_sync(0xFFFFFFFFu, syy, 1);
    sxy += __shfl_xor_sync(0xFFFFFFFFu, sxy, 1);

    if (j == 0) {
        const float inv_n   = 1.0f / 64.0f;
        const float inv_nm1 = 1.0f / 63.0f;
        const float mx = sx * inv_n;
        const float my = sy * inv_n;
        const float vx = fmaxf((sxx - 64.0f * mx * mx) * inv_nm1, 0.0f);
        const float vy = fmaxf((syy - 64.0f * my * my) * inv_nm1, 0.0f);
        const float fx = 1.0f / (sqrtf(vx) + EPS);
        const float fy = 1.0f / (sqrtf(vy) + EPS);
        const float cov = sxy - 64.0f * mx * my;     // sum (x-mx)(y-my)
        // sum (xhat - yhat)^2 = 63*vx*fx^2 + 63*vy*fy^2 - 2*cov*fx*fy
        const float ss = 63.0f * vx * fx * fx
                       + 63.0f * vy * fy * fy
                       - 2.0f * cov * fx * fy;

        out[row] = __expf(-ss) + q * q;
    }
}

extern "C" void kernel_launch(void* const* d_in, const int* in_sizes, int n_in,
                              void* d_out, int out_size)
{
    const float* x = (const float*)d_in[0];
    const float* y = (const float*)d_in[1];
    float* out = (float*)d_out;
    const int B = in_sizes[0] / 64;

    const int threads = 256;                     // 8 warps -> 128 rows per block
    const int rows_per_block = (threads / 32) * 16;
    const int blocks = (B + rows_per_block - 1) / rows_per_block;
    hybrid_rbf_kernel<<<blocks, threads>>>(x, y, out, B);
}

// round 9
// speedup vs baseline: 1.0699x; 1.0699x over previous
#include <cuda_runtime.h>
#include <math.h>

#define EPS 1e-8f

// R6 winner (80.4us) with the 256-bit loads routed through the read-only
// (non-coherent) path: ld.global.nc.v8.b32. Inputs are read-only for the
// entire kernel, so .nc is safe. Everything else identical to R6.
__device__ __forceinline__ void ldg256_nc(const float* __restrict__ p, float r[8]) {
    unsigned u0, u1, u2, u3, u4, u5, u6, u7;
    asm("ld.global.nc.v8.b32 {%0,%1,%2,%3,%4,%5,%6,%7}, [%8];"
        : "=r"(u0), "=r"(u1), "=r"(u2), "=r"(u3),
          "=r"(u4), "=r"(u5), "=r"(u6), "=r"(u7)
        : "l"(p));
    r[0] = __uint_as_float(u0); r[1] = __uint_as_float(u1);
    r[2] = __uint_as_float(u2); r[3] = __uint_as_float(u3);
    r[4] = __uint_as_float(u4); r[5] = __uint_as_float(u5);
    r[6] = __uint_as_float(u6); r[7] = __uint_as_float(u7);
}

__global__ void __launch_bounds__(256) hybrid_rbf_kernel(
    const float* __restrict__ x,
    const float* __restrict__ y,
    float* __restrict__ out,
    int B)
{
    const int warp_id = (blockIdx.x * blockDim.x + threadIdx.x) >> 5;
    const int lane    = threadIdx.x & 31;
    const int group   = lane >> 2;   // 0..7 : which row within the warp
    const int j       = lane & 3;    // 0..3 : 16-column slice within the row
    const int row     = warp_id * 8 + group;
    if (row >= B) return;

    const float* __restrict__ xp = x + (size_t)row * 64 + j * 16;
    const float* __restrict__ yp = y + (size_t)row * 64 + j * 16;

    // Issue all 4 x 256-bit loads up front
    float xa[16], ya[16];
    ldg256_nc(xp,     xa);
    ldg256_nc(xp + 8, xa + 8);
    ldg256_nc(yp,     ya);
    ldg256_nc(yp + 8, ya + 8);

    // Fused single-pass moments: Sx, Sxx, Sy, Syy, Sxy
    float sx = 0.f, sxx = 0.f, sy = 0.f, syy = 0.f, sxy = 0.f;
    #pragma unroll
    for (int e = 0; e < 16; e++) {
        const float xv = xa[e], yv = ya[e];
        sx  += xv;
        sy  += yv;
        sxx = fmaf(xv, xv, sxx);
        syy = fmaf(yv, yv, syy);
        sxy = fmaf(xv, yv, sxy);
    }

    // Quantum term (predicated: only the 8 j==0 lanes run the MUFUs),
    // hoisted before the shuffles so the load registers retire early.
    float q = 0.f;
    if (j == 0) {
        q = __cosf(xa[0] - ya[0]) * __cosf(xa[1] - ya[1])
          * __cosf(xa[2] - ya[2]) * __cosf(xa[3] - ya[3])
          * __cosf(xa[4] - ya[4]) * __cosf(xa[5] - ya[5])
          * __cosf(xa[6] - ya[6]) * __cosf(xa[7] - ya[7]);
    }

    // Segmented butterfly reduction over the aligned 4-lane group
    #pragma unroll
    for (int o = 1; o <= 2; o <<= 1) {
        sx  += __shfl_xor_sync(0xFFFFFFFFu, sx,  o);
        sy  += __shfl_xor_sync(0xFFFFFFFFu, sy,  o);
        sxx += __shfl_xor_sync(0xFFFFFFFFu, sxx, o);
        syy += __shfl_xor_sync(0xFFFFFFFFu, syy, o);
        sxy += __shfl_xor_sync(0xFFFFFFFFu, sxy, o);
    }

    if (j == 0) {
        const float inv_n   = 1.0f / 64.0f;
        const float inv_nm1 = 1.0f / 63.0f;
        const float mx = sx * inv_n;
        const float my = sy * inv_n;
        const float vx = fmaxf((sxx - 64.0f * mx * mx) * inv_nm1, 0.0f);
        const float vy = fmaxf((syy - 64.0f * my * my) * inv_nm1, 0.0f);
        const float fx = 1.0f / (sqrtf(vx) + EPS);
        const float fy = 1.0f / (sqrtf(vy) + EPS);
        const float cov = sxy - 64.0f * mx * my;     // sum (x-mx)(y-my)
        // sum (xhat - yhat)^2 = 63*vx*fx^2 + 63*vy*fy^2 - 2*cov*fx*fy
        const float ss = 63.0f * vx * fx * fx
                       + 63.0f * vy * fy * fy
                       - 2.0f * cov * fx * fy;

        out[row] = __expf(-ss) + q * q;
    }
}

extern "C" void kernel_launch(void* const* d_in, const int* in_sizes, int n_in,
                              void* d_out, int out_size)
{
    const float* x = (const float*)d_in[0];
    const float* y = (const float*)d_in[1];
    float* out = (float*)d_out;
    const int B = in_sizes[0] / 64;

    const int threads = 256;                    // 8 warps -> 64 rows per block
    const int rows_per_block = (threads / 32) * 8;
    const int blocks = (B + rows_per_block - 1) / rows_per_block;
    hybrid_rbf_kernel<<<blocks, threads>>>(x, y, out, B);
}

// round 10
// speedup vs baseline: 1.0797x; 1.0092x over previous
#include <cuda_runtime.h>
#include <math.h>

#define EPS 1e-8f

// Final form: R6 structure (one warp = 8 rows, 4 lanes/row, 16 cols/lane via
// 2 x 256-bit loads) + read-only path + L2::evict_first streaming hint.
// Data is streamed exactly once; evict_first frees L2 ways immediately.
__device__ __forceinline__ void ldg256_stream(const float* __restrict__ p, float r[8]) {
    unsigned u0, u1, u2, u3, u4, u5, u6, u7;
    asm("ld.global.nc.L2::evict_first.v8.b32 {%0,%1,%2,%3,%4,%5,%6,%7}, [%8];"
        : "=r"(u0), "=r"(u1), "=r"(u2), "=r"(u3),
          "=r"(u4), "=r"(u5), "=r"(u6), "=r"(u7)
        : "l"(p));
    r[0] = __uint_as_float(u0); r[1] = __uint_as_float(u1);
    r[2] = __uint_as_float(u2); r[3] = __uint_as_float(u3);
    r[4] = __uint_as_float(u4); r[5] = __uint_as_float(u5);
    r[6] = __uint_as_float(u6); r[7] = __uint_as_float(u7);
}

__global__ void __launch_bounds__(256) hybrid_rbf_kernel(
    const float* __restrict__ x,
    const float* __restrict__ y,
    float* __restrict__ out,
    int B)
{
    const int warp_id = (blockIdx.x * blockDim.x + threadIdx.x) >> 5;
    const int lane    = threadIdx.x & 31;
    const int group   = lane >> 2;   // 0..7 : which row within the warp
    const int j       = lane & 3;    // 0..3 : 16-column slice within the row
    const int row     = warp_id * 8 + group;
    if (row >= B) return;

    const float* __restrict__ xp = x + (size_t)row * 64 + j * 16;
    const float* __restrict__ yp = y + (size_t)row * 64 + j * 16;

    // Issue all 4 x 256-bit loads up front
    float xa[16], ya[16];
    ldg256_stream(xp,     xa);
    ldg256_stream(xp + 8, xa + 8);
    ldg256_stream(yp,     ya);
    ldg256_stream(yp + 8, ya + 8);

    // Fused single-pass moments: Sx, Sxx, Sy, Syy, Sxy
    float sx = 0.f, sxx = 0.f, sy = 0.f, syy = 0.f, sxy = 0.f;
    #pragma unroll
    for (int e = 0; e < 16; e++) {
        const float xv = xa[e], yv = ya[e];
        sx  += xv;
        sy  += yv;
        sxx = fmaf(xv, xv, sxx);
        syy = fmaf(yv, yv, syy);
        sxy = fmaf(xv, yv, sxy);
    }

    // Quantum term (predicated: only the 8 j==0 lanes run the MUFUs),
    // hoisted before the shuffles so the load registers retire early.
    float q = 0.f;
    if (j == 0) {
        q = __cosf(xa[0] - ya[0]) * __cosf(xa[1] - ya[1])
          * __cosf(xa[2] - ya[2]) * __cosf(xa[3] - ya[3])
          * __cosf(xa[4] - ya[4]) * __cosf(xa[5] - ya[5])
          * __cosf(xa[6] - ya[6]) * __cosf(xa[7] - ya[7]);
    }

    // Segmented butterfly reduction over the aligned 4-lane group
    #pragma unroll
    for (int o = 1; o <= 2; o <<= 1) {
        sx  += __shfl_xor_sync(0xFFFFFFFFu, sx,  o);
        sy  += __shfl_xor_sync(0xFFFFFFFFu, sy,  o);
        sxx += __shfl_xor_sync(0xFFFFFFFFu, sxx, o);
        syy += __shfl_xor_sync(0xFFFFFFFFu, syy, o);
        sxy += __shfl_xor_sync(0xFFFFFFFFu, sxy, o);
    }

    if (j == 0) {
        const float inv_n   = 1.0f / 64.0f;
        const float inv_nm1 = 1.0f / 63.0f;
        const float mx = sx * inv_n;
        const float my = sy * inv_n;
        const float vx = fmaxf((sxx - 64.0f * mx * mx) * inv_nm1, 0.0f);
        const float vy = fmaxf((syy - 64.0f * my * my) * inv_nm1, 0.0f);
        const float fx = 1.0f / (sqrtf(vx) + EPS);
        const float fy = 1.0f / (sqrtf(vy) + EPS);
        const float cov = sxy - 64.0f * mx * my;     // sum (x-mx)(y-my)
        // sum (xhat - yhat)^2 = 63*vx*fx^2 + 63*vy*fy^2 - 2*cov*fx*fy
        const float ss = 63.0f * vx * fx * fx
                       + 63.0f * vy * fy * fy
                       - 2.0f * cov * fx * fy;

        out[row] = __expf(-ss) + q * q;
    }
}

extern "C" void kernel_launch(void* const* d_in, const int* in_sizes, int n_in,
                              void* d_out, int out_size)
{
    const float* x = (const float*)d_in[0];
    const float* y = (const float*)d_in[1];
    float* out = (float*)d_out;
    const int B = in_sizes[0] / 64;

    const int threads = 256;                    // 8 warps -> 64 rows per block
    const int rows_per_block = (threads / 32) * 8;
    const int blocks = (B + rows_per_block - 1) / rows_per_block;
    hybrid_rbf_kernel<<<blocks, threads>>>(x, y, out, B);
}

// round 11
// speedup vs baseline: 1.0982x; 1.0171x over previous
#include <cuda_runtime.h>
#include <math.h>

#define EPS 1e-8f

__device__ __forceinline__ void ldg256_stream(const float* __restrict__ p, float r[8]) {
    unsigned u0, u1, u2, u3, u4, u5, u6, u7;
    asm("ld.global.nc.L2::evict_first.v8.b32 {%0,%1,%2,%3,%4,%5,%6,%7}, [%8];"
        : "=r"(u0), "=r"(u1), "=r"(u2), "=r"(u3),
          "=r"(u4), "=r"(u5), "=r"(u6), "=r"(u7)
        : "l"(p));
    r[0] = __uint_as_float(u0); r[1] = __uint_as_float(u1);
    r[2] = __uint_as_float(u2); r[3] = __uint_as_float(u3);
    r[4] = __uint_as_float(u4); r[5] = __uint_as_float(u5);
    r[6] = __uint_as_float(u6); r[7] = __uint_as_float(u7);
}

// R10 winner structure, but each thread processes TWO row-groups (row and
// row + rows_half) with all 8 x 256-bit loads issued before any compute:
// doubles per-warp front-batched MLP (4 -> 8) at the cost of occupancy.
__global__ void __launch_bounds__(256) hybrid_rbf_kernel(
    const float* __restrict__ x,
    const float* __restrict__ y,
    float* __restrict__ out,
    int B,
    int rows_half)   // number of rows handled by the first tile of each thread
{
    const int warp_id = (blockIdx.x * blockDim.x + threadIdx.x) >> 5;
    const int lane    = threadIdx.x & 31;
    const int group   = lane >> 2;   // 0..7 : row within the warp
    const int j       = lane & 3;    // 0..3 : 16-column slice within the row
    const int row0    = warp_id * 8 + group;
    if (row0 >= rows_half) return;
    const int row1    = row0 + rows_half;   // second tile (may be >= B at tail)
    const bool has1   = (row1 < B);

    const float* __restrict__ xp0 = x + (size_t)row0 * 64 + j * 16;
    const float* __restrict__ yp0 = y + (size_t)row0 * 64 + j * 16;
    const float* __restrict__ xp1 = x + (size_t)row1 * 64 + j * 16;
    const float* __restrict__ yp1 = y + (size_t)row1 * 64 + j * 16;

    // Issue ALL loads up front: 8 independent 256-bit loads per thread.
    float xa0[16], ya0[16], xa1[16], ya1[16];
    ldg256_stream(xp0,     xa0);
    ldg256_stream(xp0 + 8, xa0 + 8);
    ldg256_stream(yp0,     ya0);
    ldg256_stream(yp0 + 8, ya0 + 8);
    if (has1) {
        ldg256_stream(xp1,     xa1);
        ldg256_stream(xp1 + 8, xa1 + 8);
        ldg256_stream(yp1,     ya1);
        ldg256_stream(yp1 + 8, ya1 + 8);
    }

    // ---- Tile 0 moments ----
    float sx0 = 0.f, sxx0 = 0.f, sy0 = 0.f, syy0 = 0.f, sxy0 = 0.f;
    #pragma unroll
    for (int e = 0; e < 16; e++) {
        const float xv = xa0[e], yv = ya0[e];
        sx0  += xv;  sy0 += yv;
        sxx0 = fmaf(xv, xv, sxx0);
        syy0 = fmaf(yv, yv, syy0);
        sxy0 = fmaf(xv, yv, sxy0);
    }
    float q0 = 0.f;
    if (j == 0) {
        q0 = __cosf(xa0[0] - ya0[0]) * __cosf(xa0[1] - ya0[1])
           * __cosf(xa0[2] - ya0[2]) * __cosf(xa0[3] - ya0[3])
           * __cosf(xa0[4] - ya0[4]) * __cosf(xa0[5] - ya0[5])
           * __cosf(xa0[6] - ya0[6]) * __cosf(xa0[7] - ya0[7]);
    }

    // ---- Tile 1 moments ----
    float sx1 = 0.f, sxx1 = 0.f, sy1 = 0.f, syy1 = 0.f, sxy1 = 0.f;
    float q1 = 0.f;
    if (has1) {
        #pragma unroll
        for (int e = 0; e < 16; e++) {
            const float xv = xa1[e], yv = ya1[e];
            sx1  += xv;  sy1 += yv;
            sxx1 = fmaf(xv, xv, sxx1);
            syy1 = fmaf(yv, yv, syy1);
            sxy1 = fmaf(xv, yv, sxy1);
        }
        if (j == 0) {
            q1 = __cosf(xa1[0] - ya1[0]) * __cosf(xa1[1] - ya1[1])
               * __cosf(xa1[2] - ya1[2]) * __cosf(xa1[3] - ya1[3])
               * __cosf(xa1[4] - ya1[4]) * __cosf(xa1[5] - ya1[5])
               * __cosf(xa1[6] - ya1[6]) * __cosf(xa1[7] - ya1[7]);
        }
    }

    // Segmented butterfly reductions (both tiles share the shuffle steps)
    #pragma unroll
    for (int o = 1; o <= 2; o <<= 1) {
        sx0  += __shfl_xor_sync(0xFFFFFFFFu, sx0,  o);
        sy0  += __shfl_xor_sync(0xFFFFFFFFu, sy0,  o);
        sxx0 += __shfl_xor_sync(0xFFFFFFFFu, sxx0, o);
        syy0 += __shfl_xor_sync(0xFFFFFFFFu, syy0, o);
        sxy0 += __shfl_xor_sync(0xFFFFFFFFu, sxy0, o);
        sx1  += __shfl_xor_sync(0xFFFFFFFFu, sx1,  o);
        sy1  += __shfl_xor_sync(0xFFFFFFFFu, sy1,  o);
        sxx1 += __shfl_xor_sync(0xFFFFFFFFu, sxx1, o);
        syy1 += __shfl_xor_sync(0xFFFFFFFFu, syy1, o);
        sxy1 += __shfl_xor_sync(0xFFFFFFFFu, sxy1, o);
    }

    if (j == 0) {
        const float inv_n   = 1.0f / 64.0f;
        const float inv_nm1 = 1.0f / 63.0f;
        {
            const float mx = sx0 * inv_n, my = sy0 * inv_n;
            const float vx = fmaxf((sxx0 - 64.0f * mx * mx) * inv_nm1, 0.0f);
            const float vy = fmaxf((syy0 - 64.0f * my * my) * inv_nm1, 0.0f);
            const float fx = 1.0f / (sqrtf(vx) + EPS);
            const float fy = 1.0f / (sqrtf(vy) + EPS);
            const float cov = sxy0 - 64.0f * mx * my;
            const float ss = 63.0f * vx * fx * fx + 63.0f * vy * fy * fy
                           - 2.0f * cov * fx * fy;
            out[row0] = __expf(-ss) + q0 * q0;
        }
        if (has1) {
            const float mx = sx1 * inv_n, my = sy1 * inv_n;
            const float vx = fmaxf((sxx1 - 64.0f * mx * mx) * inv_nm1, 0.0f);
            const float vy = fmaxf((syy1 - 64.0f * my * my) * inv_nm1, 0.0f);
            const float fx = 1.0f / (sqrtf(vx) + EPS);
            const float fy = 1.0f / (sqrtf(vy) + EPS);
            const float cov = sxy1 - 64.0f * mx * my;
            const float ss = 63.0f * vx * fx * fx + 63.0f * vy * fy * fy
                           - 2.0f * cov * fx * fy;
            out[row1] = __expf(-ss) + q1 * q1;
        }
    }
}

extern "C" void kernel_launch(void* const* d_in, const int* in_sizes, int n_in,
                              void* d_out, int out_size)
{
    const float* x = (const float*)d_in[0];
    const float* y = (const float*)d_in[1];
    float* out = (float*)d_out;
    const int B = in_sizes[0] / 64;

    const int rows_half = (B + 1) / 2;          // first-tile row count
    const int threads = 256;                    // 8 warps -> 64 first-tile rows/block
    const int rows_per_block = (threads / 32) * 8;
    const int blocks = (rows_half + rows_per_block - 1) / rows_per_block;
    hybrid_rbf_kernel<<<blocks, threads>>>(x, y, out, B, rows_half);
}

// round 12
// speedup vs baseline: 1.1009x; 1.0025x over previous
#include <cuda_runtime.h>
#include <math.h>

#define EPS 1e-8f
#define T 3   // tiles (rows) per thread-group

__device__ __forceinline__ void ldg256_stream(const float* __restrict__ p, float r[8]) {
    unsigned u0, u1, u2, u3, u4, u5, u6, u7;
    asm("ld.global.nc.L2::evict_first.v8.b32 {%0,%1,%2,%3,%4,%5,%6,%7}, [%8];"
        : "=r"(u0), "=r"(u1), "=r"(u2), "=r"(u3),
          "=r"(u4), "=r"(u5), "=r"(u6), "=r"(u7)
        : "l"(p));
    r[0] = __uint_as_float(u0); r[1] = __uint_as_float(u1);
    r[2] = __uint_as_float(u2); r[3] = __uint_as_float(u3);
    r[4] = __uint_as_float(u4); r[5] = __uint_as_float(u5);
    r[6] = __uint_as_float(u6); r[7] = __uint_as_float(u7);
}

// R11 winner extended to 3 tiles/thread: 12 front-batched 256-bit loads per
// thread (MLP 8 -> 12). One warp = 8 row-slots; 4 lanes/row; 16 cols/lane.
__global__ void __launch_bounds__(256) hybrid_rbf_kernel(
    const float* __restrict__ x,
    const float* __restrict__ y,
    float* __restrict__ out,
    int B,
    int rows_part)   // rows per tile partition
{
    const int warp_id = (blockIdx.x * blockDim.x + threadIdx.x) >> 5;
    const int lane    = threadIdx.x & 31;
    const int group   = lane >> 2;   // 0..7 : row slot within the warp
    const int j       = lane & 3;    // 0..3 : 16-column slice within the row
    const int row0    = warp_id * 8 + group;
    if (row0 >= rows_part) return;

    int   rows[T];
    bool  has [T];
    #pragma unroll
    for (int t = 0; t < T; t++) {
        rows[t] = row0 + t * rows_part;
        has[t]  = (rows[t] < B);
    }

    // Issue ALL loads up front: up to 12 independent 256-bit loads per thread.
    float xa[T][16], ya[T][16];
    #pragma unroll
    for (int t = 0; t < T; t++) {
        if (has[t]) {
            const float* __restrict__ xp = x + (size_t)rows[t] * 64 + j * 16;
            const float* __restrict__ yp = y + (size_t)rows[t] * 64 + j * 16;
            ldg256_stream(xp,     xa[t]);
            ldg256_stream(xp + 8, xa[t] + 8);
            ldg256_stream(yp,     ya[t]);
            ldg256_stream(yp + 8, ya[t] + 8);
        }
    }

    // Moments + quantum per tile
    float sx[T], sy[T], sxx[T], syy[T], sxy[T], q[T];
    #pragma unroll
    for (int t = 0; t < T; t++) {
        sx[t] = sy[t] = sxx[t] = syy[t] = sxy[t] = 0.f;
        q[t] = 0.f;
        if (has[t]) {
            #pragma unroll
            for (int e = 0; e < 16; e++) {
                const float xv = xa[t][e], yv = ya[t][e];
                sx[t]  += xv;  sy[t] += yv;
                sxx[t] = fmaf(xv, xv, sxx[t]);
                syy[t] = fmaf(yv, yv, syy[t]);
                sxy[t] = fmaf(xv, yv, sxy[t]);
            }
            if (j == 0) {
                q[t] = __cosf(xa[t][0] - ya[t][0]) * __cosf(xa[t][1] - ya[t][1])
                     * __cosf(xa[t][2] - ya[t][2]) * __cosf(xa[t][3] - ya[t][3])
                     * __cosf(xa[t][4] - ya[t][4]) * __cosf(xa[t][5] - ya[t][5])
                     * __cosf(xa[t][6] - ya[t][6]) * __cosf(xa[t][7] - ya[t][7]);
            }
        }
    }

    // Segmented butterfly reductions over the aligned 4-lane group
    #pragma unroll
    for (int o = 1; o <= 2; o <<= 1) {
        #pragma unroll
        for (int t = 0; t < T; t++) {
            sx[t]  += __shfl_xor_sync(0xFFFFFFFFu, sx[t],  o);
            sy[t]  += __shfl_xor_sync(0xFFFFFFFFu, sy[t],  o);
            sxx[t] += __shfl_xor_sync(0xFFFFFFFFu, sxx[t], o);
            syy[t] += __shfl_xor_sync(0xFFFFFFFFu, syy[t], o);
            sxy[t] += __shfl_xor_sync(0xFFFFFFFFu, sxy[t], o);
        }
    }

    if (j == 0) {
        const float inv_n   = 1.0f / 64.0f;
        const float inv_nm1 = 1.0f / 63.0f;
        #pragma unroll
        for (int t = 0; t < T; t++) {
            if (has[t]) {
                const float mx = sx[t] * inv_n, my = sy[t] * inv_n;
                const float vx = fmaxf((sxx[t] - 64.0f * mx * mx) * inv_nm1, 0.0f);
                const float vy = fmaxf((syy[t] - 64.0f * my * my) * inv_nm1, 0.0f);
                const float fx = 1.0f / (sqrtf(vx) + EPS);
                const float fy = 1.0f / (sqrtf(vy) + EPS);
                const float cov = sxy[t] - 64.0f * mx * my;
                const float ss = 63.0f * vx * fx * fx + 63.0f * vy * fy * fy
                               - 2.0f * cov * fx * fy;
                out[rows[t]] = __expf(-ss) + q[t] * q[t];
            }
        }
    }
}

extern "C" void kernel_launch(void* const* d_in, const int* in_sizes, int n_in,
                              void* d_out, int out_size)
{
    const float* x = (const float*)d_in[0];
    const float* y = (const float*)d_in[1];
    float* out = (float*)d_out;
    const int B = in_sizes[0] / 64;

    const int rows_part = (B + T - 1) / T;       // rows per tile partition
    const int threads = 256;                     // 8 warps -> 64 slots per block
    const int rows_per_block = (threads / 32) * 8;
    const int blocks = (rows_part + rows_per_block - 1) / rows_per_block;
    hybrid_rbf_kernel<<<blocks, threads>>>(x, y, out, B, rows_part);
}